// round 2
// baseline (speedup 1.0000x reference)
#include <cuda_runtime.h>
#include <math.h>

#define B_N   16384
#define D_N   2048
#define E_N   10
#define H1_N  512
#define H2_N  64
#define OUT_N 2

#define TM      32          // samples per tile
#define KC      16          // K-chunk
#define THREADS 256
#define MAX_TILES (B_N / TM + E_N)   // 522 upper bound
#define HP      516         // padded pitch for h1 in smem
#define H2P     68          // padded pitch for h2 in smem

// ---------------- routing scratch (device globals; no allocs allowed) -----
__device__ int g_expert_offset[E_N + 1];
__device__ int g_cursor[E_N];
__device__ int g_sorted_idx[B_N];
__device__ int g_tile_expert[MAX_TILES];
__device__ int g_tile_start[MAX_TILES];
__device__ int g_tile_rows[MAX_TILES];
__device__ int g_num_tiles;

// ---------------- kernel 1: histogram + offsets + tile table --------------
__global__ void route_build(const int* __restrict__ y) {
    __shared__ int cnt[E_N];
    int t = threadIdx.x;
    if (t < E_N) cnt[t] = 0;
    __syncthreads();
    for (int i = t; i < B_N; i += blockDim.x) atomicAdd(&cnt[y[i]], 1);
    __syncthreads();
    if (t == 0) {
        int off = 0, nt = 0;
        for (int e = 0; e < E_N; e++) {
            g_expert_offset[e] = off;
            g_cursor[e] = off;
            int c = cnt[e];
            for (int s = 0; s < c; s += TM) {
                g_tile_expert[nt] = e;
                g_tile_start[nt]  = off + s;
                g_tile_rows[nt]   = (c - s) < TM ? (c - s) : TM;
                nt++;
            }
            off += c;
        }
        g_expert_offset[E_N] = off;
        g_num_tiles = nt;
    }
}

// ---------------- kernel 2: scatter sample indices by expert --------------
__global__ void route_scatter(const int* __restrict__ y) {
    int i = blockIdx.x * blockDim.x + threadIdx.x;
    if (i < B_N) {
        int pos = atomicAdd(&g_cursor[y[i]], 1);
        g_sorted_idx[pos] = i;
    }
}

// ---------------- kernel 3: fused expert GEMM + MLP head + softmax --------
// smem layout (floats):
//   region A: ws[KC*H1_N] (8192)  +  xs[KC*TM] (512)        -> 8704 floats
//             (region A is reused for W2 staging in the epilogue)
//   region B: hs[TM*HP] (16512 floats)
// total = 25216 floats = 100864 bytes
#define SMEM_FLOATS (KC * H1_N + KC * TM + TM * HP)

__global__ void __launch_bounds__(THREADS, 2)
fused_expert_mlp(const float* __restrict__ x,
                 const float* __restrict__ W1,
                 const float* __restrict__ b1,
                 const float* __restrict__ W2,
                 const float* __restrict__ b2,
                 const float* __restrict__ W3,
                 const float* __restrict__ b3,
                 float* __restrict__ out)
{
    int bid = blockIdx.x;
    if (bid >= g_num_tiles) return;

    const int e     = g_tile_expert[bid];
    const int start = g_tile_start[bid];
    const int rows  = g_tile_rows[bid];

    extern __shared__ float smem[];
    float* ws = smem;                       // [KC][H1_N]
    float* xs = smem + KC * H1_N;           // [KC][TM] (transposed x tile)
    float* hs = smem + KC * H1_N + KC * TM; // [TM][HP]

    const int tid = threadIdx.x;
    const int tx  = tid & 31;   // column lane (cols tx + 32*j)
    const int ty  = tid >> 5;   // sample group (samples ty*4 .. ty*4+3)

    __shared__ int ridx[TM];
    if (tid < TM) {
        int r = tid < rows ? tid : (rows - 1);
        ridx[tid] = g_sorted_idx[start + r];
    }
    __syncthreads();

    const float* W1e = W1 + (size_t)e * D_N * H1_N;

    float acc[4][16];
#pragma unroll
    for (int i = 0; i < 4; i++)
#pragma unroll
        for (int j = 0; j < 16; j++) acc[i][j] = 0.f;

    // ---------------- mainloop: h1 = x @ W1[e] ----------------
    for (int k0 = 0; k0 < D_N; k0 += KC) {
        // W1 tile: KC x 512 contiguous floats (32 KB), 8 float4 per thread
        const float4* wg  = (const float4*)(W1e + (size_t)k0 * H1_N);
        float4*       ws4 = (float4*)ws;
#pragma unroll
        for (int l = 0; l < 8; l++)
            ws4[tid + l * THREADS] = wg[tid + l * THREADS];

        // x tile: 32 rows x 16 floats (gathered), stored transposed
        if (tid < 128) {
            int r  = tid >> 2;
            int c4 = tid & 3;
            float4 v = *(const float4*)(x + (size_t)ridx[r] * D_N + k0 + c4 * 4);
            xs[(c4 * 4 + 0) * TM + r] = v.x;
            xs[(c4 * 4 + 1) * TM + r] = v.y;
            xs[(c4 * 4 + 2) * TM + r] = v.z;
            xs[(c4 * 4 + 3) * TM + r] = v.w;
        }
        __syncthreads();

#pragma unroll
        for (int k = 0; k < KC; k++) {
            float xv[4];
#pragma unroll
            for (int i = 0; i < 4; i++) xv[i] = xs[k * TM + ty * 4 + i];
#pragma unroll
            for (int j = 0; j < 16; j++) {
                float wv = ws[k * H1_N + tx + j * 32];
#pragma unroll
                for (int i = 0; i < 4; i++)
                    acc[i][j] = fmaf(xv[i], wv, acc[i][j]);
            }
        }
        __syncthreads();
    }

    // ---------------- epilogue: relu(h1 + b1) -> smem ----------------
#pragma unroll
    for (int j = 0; j < 16; j++) {
        int col  = tx + j * 32;
        float bb = b1[e * H1_N + col];
#pragma unroll
        for (int i = 0; i < 4; i++) {
            float v = acc[i][j] + bb;
            hs[(ty * 4 + i) * HP + col] = v > 0.f ? v : 0.f;
        }
    }
    __syncthreads();

    // ---------------- layer 2: h2 = relu(h1 @ W2 + b2) ----------------
    // thread -> sample s = tid>>3, column group cg = tid&7 (8 cols each)
    const int s  = tid >> 3;
    const int cg = tid & 7;
    float acc2[8];
#pragma unroll
    for (int j = 0; j < 8; j++) acc2[j] = 0.f;

    for (int kk = 0; kk < H1_N; kk += 128) {
        // stage W2 chunk [128][64] into region A (ws), 32 KB contiguous
        float4*       w2s = (float4*)ws;
        const float4* w2g = (const float4*)(W2 + kk * H2_N);
#pragma unroll
        for (int l = 0; l < 8; l++)
            w2s[tid + l * THREADS] = w2g[tid + l * THREADS];
        __syncthreads();

#pragma unroll 4
        for (int k = 0; k < 128; k++) {
            float  hv  = hs[s * HP + kk + k];
            float4 wa  = *(float4*)(ws + k * H2_N + cg * 8);
            float4 wb  = *(float4*)(ws + k * H2_N + cg * 8 + 4);
            acc2[0] = fmaf(hv, wa.x, acc2[0]);
            acc2[1] = fmaf(hv, wa.y, acc2[1]);
            acc2[2] = fmaf(hv, wa.z, acc2[2]);
            acc2[3] = fmaf(hv, wa.w, acc2[3]);
            acc2[4] = fmaf(hv, wb.x, acc2[4]);
            acc2[5] = fmaf(hv, wb.y, acc2[5]);
            acc2[6] = fmaf(hv, wb.z, acc2[6]);
            acc2[7] = fmaf(hv, wb.w, acc2[7]);
        }
        __syncthreads();
    }

    // h2 with bias + relu -> smem (region A now free)
    float* h2s = ws;   // [TM][H2P]
#pragma unroll
    for (int j = 0; j < 8; j++) {
        float v = acc2[j] + b2[cg * 8 + j];
        h2s[s * H2P + cg * 8 + j] = v > 0.f ? v : 0.f;
    }
    __syncthreads();

    // ---------------- layer 3 + softmax (one thread per sample) ------
    if (tid < TM && tid < rows) {
        float l0 = b3[0], l1 = b3[1];
        const float* hr = h2s + tid * H2P;
#pragma unroll
        for (int c = 0; c < H2_N; c++) {
            float hv = hr[c];
            l0 = fmaf(hv, W3[c * 2 + 0], l0);
            l1 = fmaf(hv, W3[c * 2 + 1], l1);
        }
        float m  = fmaxf(l0, l1);
        float e0 = expf(l0 - m);
        float e1 = expf(l1 - m);
        float inv = 1.f / (e0 + e1);
        int orig = ridx[tid];
        out[orig * 2 + 0] = e0 * inv;
        out[orig * 2 + 1] = e1 * inv;
    }
}

// ---------------- launch ---------------------------------------------------
extern "C" void kernel_launch(void* const* d_in, const int* in_sizes, int n_in,
                              void* d_out, int out_size)
{
    const float* x  = (const float*)d_in[0];
    const int*   y  = (const int*)  d_in[1];
    const float* W1 = (const float*)d_in[2];
    const float* b1 = (const float*)d_in[3];
    const float* W2 = (const float*)d_in[4];
    const float* b2 = (const float*)d_in[5];
    const float* W3 = (const float*)d_in[6];
    const float* b3 = (const float*)d_in[7];
    float* out = (float*)d_out;

    size_t smem_bytes = SMEM_FLOATS * sizeof(float);   // 100864 B
    cudaFuncSetAttribute(fused_expert_mlp,
                         cudaFuncAttributeMaxDynamicSharedMemorySize,
                         (int)smem_bytes);

    route_build<<<1, 256>>>(y);
    route_scatter<<<(B_N + 255) / 256, 256>>>(y);
    fused_expert_mlp<<<MAX_TILES, THREADS, smem_bytes>>>(
        x, W1, b1, W2, b2, W3, b3, out);
}